// round 1
// baseline (speedup 1.0000x reference)
#include <cuda_runtime.h>
#include <cstdint>

// Problem constants
#define A_  10
#define B_  32
#define FS_ 2
#define FD_ 8
#define H_  512
#define H3_ 1536
#define S_  512
#define KSPL 4   // k-split for gh GEMM
#define CSPL 4   // k-split for c GEMM

#define OUT_HH_OFF (A_*B_*S_)   // probs [A,B,S] first, then hh [A,B,H]

// ---------------- scratch (static device globals; no allocation) -------------
__device__ float g_M1[A_*H_*2];      // Wa1@Ws
__device__ float g_M2[A_*H_*8];      // Wa2@Wd_a
__device__ float g_cc[A_*H_];        // Wa1@bs + Wa2@bd_a
__device__ float g_N1[A_*H_*2];      // Wp1@Ws
__device__ float g_N2[A_*H_*2];      // Wp2@Ws
__device__ float g_kk[A_*H_];        // (Wp1+Wp2)@bs
__device__ float g_P [A_*H3_*2];     // Wih@Wdec
__device__ float g_q [A_*H3_];       // Wih@bdec + bih
__device__ float g_ghp[KSPL*A_*B_*H3_];  // partial hh@Whh^T (no bias)
__device__ float g_cp [CSPL*A_*B_*H_];   // partial Wa3@h_new
__device__ float g_score[A_*B_*S_];
__device__ float g_p2[A_*B_*2];      // p = static @ attn   (2 floats per (a,b))

// ---------------- math helpers ----------------------------------------------
__device__ __forceinline__ float ftanh(float x) {
    // accurate-enough tanh: 1 - 2/(e^{2x}+1); abs err ~1e-7, 2 MUFU + ~4 fma ops
    x = fminf(fmaxf(x, -15.f), 15.f);
    float t = __expf(x + x);
    return fmaf(-2.f, __fdividef(1.f, t + 1.f), 1.f);
}
__device__ __forceinline__ float sigm(float x) {
    return __fdividef(1.f, 1.f + __expf(-x));
}

// =============================================================================
// K0a: fold Wih -> P [3H,2], q [3H]   (per agent)
// grid (192, A), block 256 (8 warps = 8 rows of Wih)
// =============================================================================
__global__ void k0a_fold_ih(const float* __restrict__ Wih,
                            const float* __restrict__ Wdec,
                            const float* __restrict__ bdec,
                            const float* __restrict__ bih) {
    int a = blockIdx.y;
    __shared__ float4 sDec[H_];   // {wdec0, wdec1, bdec, 0}
    for (int k = threadIdx.x; k < H_; k += blockDim.x) {
        sDec[k] = make_float4(Wdec[((size_t)a*H_ + k)*2 + 0],
                              Wdec[((size_t)a*H_ + k)*2 + 1],
                              bdec[(size_t)a*H_ + k], 0.f);
    }
    __syncthreads();
    int warp = threadIdx.x >> 5, lane = threadIdx.x & 31;
    int j = blockIdx.x * 8 + warp;
    const float* row = Wih + ((size_t)a*H3_ + j)*H_;
    float p0 = 0.f, p1 = 0.f, q = 0.f;
#pragma unroll
    for (int i = 0; i < 4; i++) {
        int k0 = lane*4 + i*128;
        float4 w4 = *(const float4*)(row + k0);
        float4 d0 = sDec[k0+0], d1 = sDec[k0+1], d2 = sDec[k0+2], d3 = sDec[k0+3];
        p0 = fmaf(w4.x,d0.x, fmaf(w4.y,d1.x, fmaf(w4.z,d2.x, fmaf(w4.w,d3.x, p0))));
        p1 = fmaf(w4.x,d0.y, fmaf(w4.y,d1.y, fmaf(w4.z,d2.y, fmaf(w4.w,d3.y, p1))));
        q  = fmaf(w4.x,d0.z, fmaf(w4.y,d1.z, fmaf(w4.z,d2.z, fmaf(w4.w,d3.z, q ))));
    }
#pragma unroll
    for (int o = 16; o; o >>= 1) {
        p0 += __shfl_down_sync(0xffffffffu, p0, o);
        p1 += __shfl_down_sync(0xffffffffu, p1, o);
        q  += __shfl_down_sync(0xffffffffu, q , o);
    }
    if (lane == 0) {
        int r = a*H3_ + j;
        g_P[r*2+0] = p0; g_P[r*2+1] = p1;
        g_q[r] = q + bih[r];
    }
}

// =============================================================================
// K0b: fold W_attn -> M1,M2,cc   and W_ptr -> N1,N2,kk   (per agent, per h)
// grid (64, A), block 256 (8 warps = 8 h-rows)
// =============================================================================
__global__ void k0b_fold_attn_ptr(const float* __restrict__ Wattn,
                                  const float* __restrict__ Wptr,
                                  const float* __restrict__ Ws,
                                  const float* __restrict__ bs,
                                  const float* __restrict__ Wd,
                                  const float* __restrict__ bd) {
    int a = blockIdx.y;
    __shared__ float4 sFold[H_];          // {ws0, ws1, bs, bd_a}
    __shared__ float4 sWdA[H_], sWdB[H_]; // Wd_a[k][0..3], [4..7]
    for (int k = threadIdx.x; k < H_; k += blockDim.x) {
        sFold[k] = make_float4(Ws[k*2+0], Ws[k*2+1], bs[k], bd[(size_t)a*H_ + k]);
        const float* wd = Wd + ((size_t)a*H_ + k)*8;
        sWdA[k] = *(const float4*)(wd);
        sWdB[k] = *(const float4*)(wd + 4);
    }
    __syncthreads();
    int warp = threadIdx.x >> 5, lane = threadIdx.x & 31;
    int h = blockIdx.x * 8 + warp;
    const float* ra = Wattn + ((size_t)a*H_ + h)*H3_;
    const float* rp = Wptr  + ((size_t)a*H_ + h)*(2*H_);
    float acc[16];
#pragma unroll
    for (int t = 0; t < 16; t++) acc[t] = 0.f;
#pragma unroll
    for (int i = 0; i < 4; i++) {
        int k0 = lane*4 + i*128;
        float4 a1 = *(const float4*)(ra + k0);
        float4 a2 = *(const float4*)(ra + H_ + k0);
        float4 q1 = *(const float4*)(rp + k0);
        float4 q2 = *(const float4*)(rp + H_ + k0);
        const float* a1p = (const float*)&a1;
        const float* a2p = (const float*)&a2;
        const float* q1p = (const float*)&q1;
        const float* q2p = (const float*)&q2;
#pragma unroll
        for (int c = 0; c < 4; c++) {
            int k = k0 + c;
            float wa1 = a1p[c], wa2 = a2p[c], wp1 = q1p[c], wp2 = q2p[c];
            float4 f  = sFold[k];
            float4 dA = sWdA[k];
            float4 dB = sWdB[k];
            acc[0]  = fmaf(wa1, f.x, acc[0]);   // M1[0]
            acc[1]  = fmaf(wa1, f.y, acc[1]);   // M1[1]
            acc[2]  = fmaf(wa2, dA.x, acc[2]);  // M2[0..7]
            acc[3]  = fmaf(wa2, dA.y, acc[3]);
            acc[4]  = fmaf(wa2, dA.z, acc[4]);
            acc[5]  = fmaf(wa2, dA.w, acc[5]);
            acc[6]  = fmaf(wa2, dB.x, acc[6]);
            acc[7]  = fmaf(wa2, dB.y, acc[7]);
            acc[8]  = fmaf(wa2, dB.z, acc[8]);
            acc[9]  = fmaf(wa2, dB.w, acc[9]);
            acc[10] = fmaf(wa1, f.z, fmaf(wa2, f.w, acc[10])); // cc
            acc[11] = fmaf(wp1, f.x, acc[11]);  // N1
            acc[12] = fmaf(wp1, f.y, acc[12]);
            acc[13] = fmaf(wp2, f.x, acc[13]);  // N2
            acc[14] = fmaf(wp2, f.y, acc[14]);
            acc[15] = fmaf(wp1 + wp2, f.z, acc[15]); // kk
        }
    }
#pragma unroll
    for (int t = 0; t < 16; t++)
#pragma unroll
        for (int o = 16; o; o >>= 1)
            acc[t] += __shfl_down_sync(0xffffffffu, acc[t], o);
    if (lane == 0) {
        int r = a*H_ + h;
        g_M1[r*2+0] = acc[0];  g_M1[r*2+1] = acc[1];
#pragma unroll
        for (int f2 = 0; f2 < 8; f2++) g_M2[r*8+f2] = acc[2+f2];
        g_cc[r] = acc[10];
        g_N1[r*2+0] = acc[11]; g_N1[r*2+1] = acc[12];
        g_N2[r*2+0] = acc[13]; g_N2[r*2+1] = acc[14];
        g_kk[r] = acc[15];
    }
}

// =============================================================================
// K1: gh partials: ghp[ks][a][b][j] = sum_{k in split ks} hh[b,k]*Whh[a,j,k]
// grid (12, KSPL, A), block 128 (thread = j within tile; 32 b-accumulators)
// =============================================================================
__global__ void k1_gh(const float* __restrict__ Whh,
                      const float* __restrict__ hh) {
    int a = blockIdx.z, ks = blockIdx.y;
    int k0 = ks * 128;
    __shared__ float sHH[128*36];   // [k_local][b], pad 36 for conflicts + f4 align
    for (int idx = threadIdx.x; idx < 32*128; idx += blockDim.x) {
        int b = idx >> 7, kl = idx & 127;
        sHH[kl*36 + b] = hh[(size_t)b*H_ + k0 + kl];
    }
    __syncthreads();
    int j = blockIdx.x * 128 + threadIdx.x;
    const float* row = Whh + ((size_t)a*H3_ + j)*H_ + k0;
    float acc[32];
#pragma unroll
    for (int b = 0; b < 32; b++) acc[b] = 0.f;

    for (int kl = 0; kl < 128; kl += 4) {
        float4 w4 = *(const float4*)(row + kl);
        const float* wp = (const float*)&w4;
#pragma unroll
        for (int c = 0; c < 4; c++) {
            float w = wp[c];
            const float4* hp = (const float4*)(sHH + (kl + c)*36);
#pragma unroll
            for (int bi = 0; bi < 8; bi++) {
                float4 h4 = hp[bi];
                acc[bi*4+0] = fmaf(w, h4.x, acc[bi*4+0]);
                acc[bi*4+1] = fmaf(w, h4.y, acc[bi*4+1]);
                acc[bi*4+2] = fmaf(w, h4.z, acc[bi*4+2]);
                acc[bi*4+3] = fmaf(w, h4.w, acc[bi*4+3]);
            }
        }
    }
    float* outp = g_ghp + ((size_t)(ks*A_ + a)*B_)*H3_ + j;
#pragma unroll
    for (int b = 0; b < 32; b++) outp[(size_t)b*H3_] = acc[b];
}

// =============================================================================
// K2: GRU gates -> h_new written directly to d_out hh region
// grid 640, block 256   (A*B*H threads)
// =============================================================================
__global__ void k2_gates(const float* __restrict__ dec,
                         const float* __restrict__ hh,
                         const float* __restrict__ bhh,
                         float* __restrict__ out) {
    int idx = blockIdx.x * blockDim.x + threadIdx.x;
    int h  = idx & (H_-1);
    int ab = idx >> 9;
    int b  = ab & (B_-1);
    int a  = ab >> 5;
    float d0 = dec[b*2+0], d1 = dec[b*2+1];
    int base = a*H3_;

    float gi[3], gh[3];
#pragma unroll
    for (int g = 0; g < 3; g++) {
        int j = base + g*H_ + h;
        gi[g] = fmaf(g_P[j*2+0], d0, fmaf(g_P[j*2+1], d1, g_q[j]));
        float s = bhh[j];
#pragma unroll
        for (int ks = 0; ks < KSPL; ks++)
            s += g_ghp[((size_t)(ks*A_ + a)*B_ + b)*H3_ + g*H_ + h];
        gh[g] = s;
    }
    float r = sigm(gi[0] + gh[0]);
    float z = sigm(gi[1] + gh[1]);
    float n = ftanh(fmaf(r, gh[2], gi[2]));
    float hprev = hh[(size_t)b*H_ + h];
    out[OUT_HH_OFF + (size_t)ab*H_ + h] = fmaf(z, hprev - n, n); // (1-z)n + z h
}

// =============================================================================
// K3: c partials: cp[cs][a][b][h] = sum_{k in split} Wa3[a,h,k]*h_new[a,b,k]
// grid (4, CSPL, A), block 128
// =============================================================================
__global__ void k3_c(const float* __restrict__ Wattn,
                     const float* __restrict__ out) {
    int a = blockIdx.z, cs = blockIdx.y;
    int k0 = cs * 128;
    __shared__ float sHN[128*36];
    const float* hn = out + OUT_HH_OFF + (size_t)a*B_*H_;
    for (int idx = threadIdx.x; idx < 32*128; idx += blockDim.x) {
        int b = idx >> 7, kl = idx & 127;
        sHN[kl*36 + b] = hn[(size_t)b*H_ + k0 + kl];
    }
    __syncthreads();
    int h = blockIdx.x * 128 + threadIdx.x;
    const float* row = Wattn + ((size_t)a*H_ + h)*H3_ + 2*H_ + k0;
    float acc[32];
#pragma unroll
    for (int b = 0; b < 32; b++) acc[b] = 0.f;

    for (int kl = 0; kl < 128; kl += 4) {
        float4 w4 = *(const float4*)(row + kl);
        const float* wp = (const float*)&w4;
#pragma unroll
        for (int c = 0; c < 4; c++) {
            float w = wp[c];
            const float4* hp = (const float4*)(sHN + (kl + c)*36);
#pragma unroll
            for (int bi = 0; bi < 8; bi++) {
                float4 h4 = hp[bi];
                acc[bi*4+0] = fmaf(w, h4.x, acc[bi*4+0]);
                acc[bi*4+1] = fmaf(w, h4.y, acc[bi*4+1]);
                acc[bi*4+2] = fmaf(w, h4.z, acc[bi*4+2]);
                acc[bi*4+3] = fmaf(w, h4.w, acc[bi*4+3]);
            }
        }
    }
    float* outp = g_cp + ((size_t)(cs*A_ + a)*B_)*H_ + h;
#pragma unroll
    for (int b = 0; b < 32; b++) outp[(size_t)b*H_] = acc[b];
}

// =============================================================================
// K4a: attention scores: score[a,b,s] = sum_h va[h]*tanh(M1.st + M2.dy + c)
// grid A*B*2 (s halves), block 256
// =============================================================================
__global__ void k4a_score(const float* __restrict__ stat,
                          const float* __restrict__ dyn,
                          const float* __restrict__ va) {
    int blk = blockIdx.x;
    int half = blk & 1, ab = blk >> 1;
    int a = ab >> 5, b = ab & 31;
    __shared__ float4 sH[H_*3];
    for (int h = threadIdx.x; h < H_; h += blockDim.x) {
        int r = a*H_ + h;
        float c = g_cc[r];
#pragma unroll
        for (int cs = 0; cs < CSPL; cs++)
            c += g_cp[((size_t)(cs*A_ + a)*B_ + b)*H_ + h];
        sH[h*3+0] = make_float4(g_M1[r*2+0], g_M1[r*2+1], g_M2[r*8+0], g_M2[r*8+1]);
        sH[h*3+1] = make_float4(g_M2[r*8+2], g_M2[r*8+3], g_M2[r*8+4], g_M2[r*8+5]);
        sH[h*3+2] = make_float4(g_M2[r*8+6], g_M2[r*8+7], c, va[r]);
    }
    __syncthreads();
    int s = half*256 + threadIdx.x;
    float st0 = stat[((size_t)b*2+0)*S_ + s];
    float st1 = stat[((size_t)b*2+1)*S_ + s];
    float dy[8];
#pragma unroll
    for (int f = 0; f < 8; f++)
        dy[f] = dyn[(((size_t)a*B_ + b)*FD_ + f)*S_ + s];

    float score = 0.f;
#pragma unroll 4
    for (int h = 0; h < H_; h++) {
        float4 p0 = sH[h*3+0], p1 = sH[h*3+1], p2 = sH[h*3+2];
        float ea = fmaf(p0.x, st0, fmaf(p0.y, st1, p2.z));
        float eb = fmaf(p0.z, dy[0], fmaf(p0.w, dy[1], fmaf(p1.x, dy[2], p1.y*dy[3])));
        float ec = fmaf(p1.z, dy[4], fmaf(p1.w, dy[5], fmaf(p2.x, dy[6], p2.y*dy[7])));
        score = fmaf(p2.w, ftanh((ea + eb) + ec), score);
    }
    g_score[(size_t)ab*S_ + s] = score;
}

// =============================================================================
// K4b: softmax over s + p = static @ attn  (2 floats per (a,b))
// grid A*B, block 512
// =============================================================================
__global__ void k4b_softmax_p(const float* __restrict__ stat) {
    __shared__ float redM[16];
    __shared__ float redS[16][3];
    int ab = blockIdx.x;
    int b = ab & 31;
    int tid = threadIdx.x, warp = tid >> 5, lane = tid & 31;
    float v = g_score[(size_t)ab*S_ + tid];
    float m = v;
#pragma unroll
    for (int o = 16; o; o >>= 1) m = fmaxf(m, __shfl_xor_sync(0xffffffffu, m, o));
    if (lane == 0) redM[warp] = m;
    __syncthreads();
    float mx = redM[0];
#pragma unroll
    for (int w = 1; w < 16; w++) mx = fmaxf(mx, redM[w]);
    float e = __expf(v - mx);
    float st0 = stat[((size_t)b*2+0)*S_ + tid];
    float st1 = stat[((size_t)b*2+1)*S_ + tid];
    float s0 = e, s1 = e*st0, s2 = e*st1;
#pragma unroll
    for (int o = 16; o; o >>= 1) {
        s0 += __shfl_xor_sync(0xffffffffu, s0, o);
        s1 += __shfl_xor_sync(0xffffffffu, s1, o);
        s2 += __shfl_xor_sync(0xffffffffu, s2, o);
    }
    if (lane == 0) { redS[warp][0] = s0; redS[warp][1] = s1; redS[warp][2] = s2; }
    __syncthreads();
    if (tid == 0) {
        float d = 0.f, n0 = 0.f, n1 = 0.f;
#pragma unroll
        for (int w = 0; w < 16; w++) { d += redS[w][0]; n0 += redS[w][1]; n1 += redS[w][2]; }
        g_p2[ab*2+0] = n0 / d;
        g_p2[ab*2+1] = n1 / d;
    }
}

// =============================================================================
// K5: pointer head: probs[a,b,s] = sum_h vp[h]*tanh(N1.st + d[a,b,h])
// grid A*B*2, block 256
// =============================================================================
__global__ void k5_probs(const float* __restrict__ stat,
                         const float* __restrict__ vp,
                         float* __restrict__ out) {
    int blk = blockIdx.x;
    int half = blk & 1, ab = blk >> 1;
    int a = ab >> 5, b = ab & 31;
    __shared__ float4 sH[H_];
    float p0 = g_p2[ab*2+0], p1 = g_p2[ab*2+1];
    for (int h = threadIdx.x; h < H_; h += blockDim.x) {
        int r = a*H_ + h;
        float d = fmaf(g_N2[r*2+0], p0, fmaf(g_N2[r*2+1], p1, g_kk[r]));
        sH[h] = make_float4(g_N1[r*2+0], g_N1[r*2+1], d, vp[r]);
    }
    __syncthreads();
    int s = half*256 + threadIdx.x;
    float st0 = stat[((size_t)b*2+0)*S_ + s];
    float st1 = stat[((size_t)b*2+1)*S_ + s];
    float pr = 0.f;
#pragma unroll 4
    for (int h = 0; h < H_; h++) {
        float4 q = sH[h];
        pr = fmaf(q.w, ftanh(fmaf(q.x, st0, fmaf(q.y, st1, q.z))), pr);
    }
    out[(size_t)ab*S_ + s] = pr;
}

// =============================================================================
extern "C" void kernel_launch(void* const* d_in, const int* in_sizes, int n_in,
                              void* d_out, int out_size) {
    const float* stat  = (const float*)d_in[0];   // static     [B,FS,S]
    const float* dyn   = (const float*)d_in[1];   // dynamics   [A,B,FD,S]
    const float* dec   = (const float*)d_in[2];   // decoder_in [B,FS,1]
    const float* hh    = (const float*)d_in[3];   // last_hh    [B,H]
    const float* Ws    = (const float*)d_in[4];   // [H,FS]
    const float* bs    = (const float*)d_in[5];   // [H]
    const float* Wd    = (const float*)d_in[6];   // [A,H,FD]
    const float* bd    = (const float*)d_in[7];   // [A,H]
    const float* Wdec  = (const float*)d_in[8];   // [A,H,FS]
    const float* bdec  = (const float*)d_in[9];   // [A,H]
    const float* Wih   = (const float*)d_in[10];  // [A,3H,H]
    const float* Whh   = (const float*)d_in[11];  // [A,3H,H]
    const float* bih   = (const float*)d_in[12];  // [A,3H]
    const float* bhh   = (const float*)d_in[13];  // [A,3H]
    const float* va    = (const float*)d_in[14];  // [A,H]
    const float* Wattn = (const float*)d_in[15];  // [A,H,3H]
    const float* vp    = (const float*)d_in[16];  // [A,H]
    const float* Wptr  = (const float*)d_in[17];  // [A,H,2H]
    float* out = (float*)d_out;

    k0a_fold_ih      <<<dim3(192, A_), 256>>>(Wih, Wdec, bdec, bih);
    k0b_fold_attn_ptr<<<dim3(64, A_),  256>>>(Wattn, Wptr, Ws, bs, Wd, bd);
    k1_gh            <<<dim3(12, KSPL, A_), 128>>>(Whh, hh);
    k2_gates         <<<640, 256>>>(dec, hh, bhh, out);
    k3_c             <<<dim3(4, CSPL, A_), 128>>>(Wattn, out);
    k4a_score        <<<A_*B_*2, 256>>>(stat, dyn, va);
    k4b_softmax_p    <<<A_*B_, 512>>>(stat);
    k5_probs         <<<A_*B_*2, 256>>>(stat, vp, out);
}

// round 2
// speedup vs baseline: 1.3751x; 1.3751x over previous
#include <cuda_runtime.h>
#include <cstdint>

// Problem constants
#define A_  10
#define B_  32
#define FS_ 2
#define FD_ 8
#define H_  512
#define H3_ 1536
#define S_  512
#define KSPL 4   // k-split for gh GEMM
#define CSPL 4   // k-split for c GEMM

#define OUT_HH_OFF (A_*B_*S_)   // probs [A,B,S] first, then hh [A,B,H]

typedef unsigned long long u64;

// ---------------- scratch (static device globals; no allocation) -------------
__device__ float g_M1[A_*H_*2];      // Wa1@Ws
__device__ float g_M2[A_*H_*8];      // Wa2@Wd_a
__device__ float g_cc[A_*H_];        // Wa1@bs + Wa2@bd_a
__device__ float g_N1[A_*H_*2];      // Wp1@Ws
__device__ float g_N2[A_*H_*2];      // Wp2@Ws
__device__ float g_kk[A_*H_];        // (Wp1+Wp2)@bs
__device__ float g_P [A_*H3_*2];     // Wih@Wdec
__device__ float g_q [A_*H3_];       // Wih@bdec + bih
__device__ float g_ghp[KSPL*A_*B_*H3_];  // partial hh@Whh^T (no bias)
__device__ float g_cp [CSPL*A_*B_*H_];   // partial Wa3@h_new
__device__ float g_score[A_*B_*S_];
__device__ float g_p2[A_*B_*2];      // p = static @ attn   (2 floats per (a,b))

// ---------------- math helpers ----------------------------------------------
struct __align__(16) U2 { u64 x, y; };

__device__ __forceinline__ u64 pack2(float lo, float hi) {
    u64 r; asm("mov.b64 %0, {%1,%2};" : "=l"(r) : "f"(lo), "f"(hi)); return r;
}
__device__ __forceinline__ u64 bcast2(float x) { return pack2(x, x); }
__device__ __forceinline__ void unpack2(u64 v, float& lo, float& hi) {
    asm("mov.b64 {%0,%1}, %2;" : "=f"(lo), "=f"(hi) : "l"(v));
}
__device__ __forceinline__ u64 fma2(u64 a, u64 b, u64 c) {
    u64 d; asm("fma.rn.f32x2 %0, %1, %2, %3;" : "=l"(d) : "l"(a), "l"(b), "l"(c));
    return d;
}
__device__ __forceinline__ float tanh_ap(float x) {
    float y; asm("tanh.approx.f32 %0, %1;" : "=f"(y) : "f"(x)); return y;
}
__device__ __forceinline__ u64 tanh2(u64 v) {
    float a, b; unpack2(v, a, b);
    return pack2(tanh_ap(a), tanh_ap(b));
}
// precise versions for the GRU gates (h_new is an output)
__device__ __forceinline__ float ftanh(float x) {
    x = fminf(fmaxf(x, -15.f), 15.f);
    float t = __expf(x + x);
    return fmaf(-2.f, __fdividef(1.f, t + 1.f), 1.f);
}
__device__ __forceinline__ float sigm(float x) {
    return __fdividef(1.f, 1.f + __expf(-x));
}

// =============================================================================
// K0a: fold Wih -> P [3H,2], q [3H]   (per agent)
// =============================================================================
__global__ void k0a_fold_ih(const float* __restrict__ Wih,
                            const float* __restrict__ Wdec,
                            const float* __restrict__ bdec,
                            const float* __restrict__ bih) {
    int a = blockIdx.y;
    __shared__ float4 sDec[H_];
    for (int k = threadIdx.x; k < H_; k += blockDim.x) {
        sDec[k] = make_float4(Wdec[((size_t)a*H_ + k)*2 + 0],
                              Wdec[((size_t)a*H_ + k)*2 + 1],
                              bdec[(size_t)a*H_ + k], 0.f);
    }
    __syncthreads();
    int warp = threadIdx.x >> 5, lane = threadIdx.x & 31;
    int j = blockIdx.x * 8 + warp;
    const float* row = Wih + ((size_t)a*H3_ + j)*H_;
    float p0 = 0.f, p1 = 0.f, q = 0.f;
#pragma unroll
    for (int i = 0; i < 4; i++) {
        int k0 = lane*4 + i*128;
        float4 w4 = *(const float4*)(row + k0);
        float4 d0 = sDec[k0+0], d1 = sDec[k0+1], d2 = sDec[k0+2], d3 = sDec[k0+3];
        p0 = fmaf(w4.x,d0.x, fmaf(w4.y,d1.x, fmaf(w4.z,d2.x, fmaf(w4.w,d3.x, p0))));
        p1 = fmaf(w4.x,d0.y, fmaf(w4.y,d1.y, fmaf(w4.z,d2.y, fmaf(w4.w,d3.y, p1))));
        q  = fmaf(w4.x,d0.z, fmaf(w4.y,d1.z, fmaf(w4.z,d2.z, fmaf(w4.w,d3.z, q ))));
    }
#pragma unroll
    for (int o = 16; o; o >>= 1) {
        p0 += __shfl_down_sync(0xffffffffu, p0, o);
        p1 += __shfl_down_sync(0xffffffffu, p1, o);
        q  += __shfl_down_sync(0xffffffffu, q , o);
    }
    if (lane == 0) {
        int r = a*H3_ + j;
        g_P[r*2+0] = p0; g_P[r*2+1] = p1;
        g_q[r] = q + bih[r];
    }
}

// =============================================================================
// K0b: fold W_attn -> M1,M2,cc   and W_ptr -> N1,N2,kk
// =============================================================================
__global__ void k0b_fold_attn_ptr(const float* __restrict__ Wattn,
                                  const float* __restrict__ Wptr,
                                  const float* __restrict__ Ws,
                                  const float* __restrict__ bs,
                                  const float* __restrict__ Wd,
                                  const float* __restrict__ bd) {
    int a = blockIdx.y;
    __shared__ float4 sFold[H_];
    __shared__ float4 sWdA[H_], sWdB[H_];
    for (int k = threadIdx.x; k < H_; k += blockDim.x) {
        sFold[k] = make_float4(Ws[k*2+0], Ws[k*2+1], bs[k], bd[(size_t)a*H_ + k]);
        const float* wd = Wd + ((size_t)a*H_ + k)*8;
        sWdA[k] = *(const float4*)(wd);
        sWdB[k] = *(const float4*)(wd + 4);
    }
    __syncthreads();
    int warp = threadIdx.x >> 5, lane = threadIdx.x & 31;
    int h = blockIdx.x * 8 + warp;
    const float* ra = Wattn + ((size_t)a*H_ + h)*H3_;
    const float* rp = Wptr  + ((size_t)a*H_ + h)*(2*H_);
    float acc[16];
#pragma unroll
    for (int t = 0; t < 16; t++) acc[t] = 0.f;
#pragma unroll
    for (int i = 0; i < 4; i++) {
        int k0 = lane*4 + i*128;
        float4 a1 = *(const float4*)(ra + k0);
        float4 a2 = *(const float4*)(ra + H_ + k0);
        float4 q1 = *(const float4*)(rp + k0);
        float4 q2 = *(const float4*)(rp + H_ + k0);
        const float* a1p = (const float*)&a1;
        const float* a2p = (const float*)&a2;
        const float* q1p = (const float*)&q1;
        const float* q2p = (const float*)&q2;
#pragma unroll
        for (int c = 0; c < 4; c++) {
            int k = k0 + c;
            float wa1 = a1p[c], wa2 = a2p[c], wp1 = q1p[c], wp2 = q2p[c];
            float4 f  = sFold[k];
            float4 dA = sWdA[k];
            float4 dB = sWdB[k];
            acc[0]  = fmaf(wa1, f.x, acc[0]);
            acc[1]  = fmaf(wa1, f.y, acc[1]);
            acc[2]  = fmaf(wa2, dA.x, acc[2]);
            acc[3]  = fmaf(wa2, dA.y, acc[3]);
            acc[4]  = fmaf(wa2, dA.z, acc[4]);
            acc[5]  = fmaf(wa2, dA.w, acc[5]);
            acc[6]  = fmaf(wa2, dB.x, acc[6]);
            acc[7]  = fmaf(wa2, dB.y, acc[7]);
            acc[8]  = fmaf(wa2, dB.z, acc[8]);
            acc[9]  = fmaf(wa2, dB.w, acc[9]);
            acc[10] = fmaf(wa1, f.z, fmaf(wa2, f.w, acc[10]));
            acc[11] = fmaf(wp1, f.x, acc[11]);
            acc[12] = fmaf(wp1, f.y, acc[12]);
            acc[13] = fmaf(wp2, f.x, acc[13]);
            acc[14] = fmaf(wp2, f.y, acc[14]);
            acc[15] = fmaf(wp1 + wp2, f.z, acc[15]);
        }
    }
#pragma unroll
    for (int t = 0; t < 16; t++)
#pragma unroll
        for (int o = 16; o; o >>= 1)
            acc[t] += __shfl_down_sync(0xffffffffu, acc[t], o);
    if (lane == 0) {
        int r = a*H_ + h;
        g_M1[r*2+0] = acc[0];  g_M1[r*2+1] = acc[1];
#pragma unroll
        for (int f2 = 0; f2 < 8; f2++) g_M2[r*8+f2] = acc[2+f2];
        g_cc[r] = acc[10];
        g_N1[r*2+0] = acc[11]; g_N1[r*2+1] = acc[12];
        g_N2[r*2+0] = acc[13]; g_N2[r*2+1] = acc[14];
        g_kk[r] = acc[15];
    }
}

// =============================================================================
// K1: gh partials
// =============================================================================
__global__ void k1_gh(const float* __restrict__ Whh,
                      const float* __restrict__ hh) {
    int a = blockIdx.z, ks = blockIdx.y;
    int k0 = ks * 128;
    __shared__ float sHH[128*36];
    for (int idx = threadIdx.x; idx < 32*128; idx += blockDim.x) {
        int b = idx >> 7, kl = idx & 127;
        sHH[kl*36 + b] = hh[(size_t)b*H_ + k0 + kl];
    }
    __syncthreads();
    int j = blockIdx.x * 128 + threadIdx.x;
    const float* row = Whh + ((size_t)a*H3_ + j)*H_ + k0;
    float acc[32];
#pragma unroll
    for (int b = 0; b < 32; b++) acc[b] = 0.f;

    for (int kl = 0; kl < 128; kl += 4) {
        float4 w4 = *(const float4*)(row + kl);
        const float* wp = (const float*)&w4;
#pragma unroll
        for (int c = 0; c < 4; c++) {
            float w = wp[c];
            const float4* hp = (const float4*)(sHH + (kl + c)*36);
#pragma unroll
            for (int bi = 0; bi < 8; bi++) {
                float4 h4 = hp[bi];
                acc[bi*4+0] = fmaf(w, h4.x, acc[bi*4+0]);
                acc[bi*4+1] = fmaf(w, h4.y, acc[bi*4+1]);
                acc[bi*4+2] = fmaf(w, h4.z, acc[bi*4+2]);
                acc[bi*4+3] = fmaf(w, h4.w, acc[bi*4+3]);
            }
        }
    }
    float* outp = g_ghp + ((size_t)(ks*A_ + a)*B_)*H3_ + j;
#pragma unroll
    for (int b = 0; b < 32; b++) outp[(size_t)b*H3_] = acc[b];
}

// =============================================================================
// K2: GRU gates -> h_new (precise math; output)
// =============================================================================
__global__ void k2_gates(const float* __restrict__ dec,
                         const float* __restrict__ hh,
                         const float* __restrict__ bhh,
                         float* __restrict__ out) {
    int idx = blockIdx.x * blockDim.x + threadIdx.x;
    int h  = idx & (H_-1);
    int ab = idx >> 9;
    int b  = ab & (B_-1);
    int a  = ab >> 5;
    float d0 = dec[b*2+0], d1 = dec[b*2+1];
    int base = a*H3_;

    float gi[3], gh[3];
#pragma unroll
    for (int g = 0; g < 3; g++) {
        int j = base + g*H_ + h;
        gi[g] = fmaf(g_P[j*2+0], d0, fmaf(g_P[j*2+1], d1, g_q[j]));
        float s = bhh[j];
#pragma unroll
        for (int ks = 0; ks < KSPL; ks++)
            s += g_ghp[((size_t)(ks*A_ + a)*B_ + b)*H3_ + g*H_ + h];
        gh[g] = s;
    }
    float r = sigm(gi[0] + gh[0]);
    float z = sigm(gi[1] + gh[1]);
    float n = ftanh(fmaf(r, gh[2], gi[2]));
    float hprev = hh[(size_t)b*H_ + h];
    out[OUT_HH_OFF + (size_t)ab*H_ + h] = fmaf(z, hprev - n, n);
}

// =============================================================================
// K3: c partials
// =============================================================================
__global__ void k3_c(const float* __restrict__ Wattn,
                     const float* __restrict__ out) {
    int a = blockIdx.z, cs = blockIdx.y;
    int k0 = cs * 128;
    __shared__ float sHN[128*36];
    const float* hn = out + OUT_HH_OFF + (size_t)a*B_*H_;
    for (int idx = threadIdx.x; idx < 32*128; idx += blockDim.x) {
        int b = idx >> 7, kl = idx & 127;
        sHN[kl*36 + b] = hn[(size_t)b*H_ + k0 + kl];
    }
    __syncthreads();
    int h = blockIdx.x * 128 + threadIdx.x;
    const float* row = Wattn + ((size_t)a*H_ + h)*H3_ + 2*H_ + k0;
    float acc[32];
#pragma unroll
    for (int b = 0; b < 32; b++) acc[b] = 0.f;

    for (int kl = 0; kl < 128; kl += 4) {
        float4 w4 = *(const float4*)(row + kl);
        const float* wp = (const float*)&w4;
#pragma unroll
        for (int c = 0; c < 4; c++) {
            float w = wp[c];
            const float4* hp = (const float4*)(sHN + (kl + c)*36);
#pragma unroll
            for (int bi = 0; bi < 8; bi++) {
                float4 h4 = hp[bi];
                acc[bi*4+0] = fmaf(w, h4.x, acc[bi*4+0]);
                acc[bi*4+1] = fmaf(w, h4.y, acc[bi*4+1]);
                acc[bi*4+2] = fmaf(w, h4.z, acc[bi*4+2]);
                acc[bi*4+3] = fmaf(w, h4.w, acc[bi*4+3]);
            }
        }
    }
    float* outp = g_cp + ((size_t)(cs*A_ + a)*B_)*H_ + h;
#pragma unroll
    for (int b = 0; b < 32; b++) outp[(size_t)b*H_] = acc[b];
}

// =============================================================================
// K4a: attention scores (f32x2 over h-pairs + tanh.approx)
// grid A*B*2 (s halves), block 128; thread handles s = base + 2t, 2t+1
// smem: 256 h-pairs x 24 floats (pairs of m10,m11,m2[0..7],c,va) = 24KB
// =============================================================================
__global__ void k4a_score(const float* __restrict__ stat,
                          const float* __restrict__ dyn,
                          const float* __restrict__ va) {
    __shared__ float sC[256*24];
    int blk = blockIdx.x;
    int half = blk & 1, ab = blk >> 1;
    int a = ab >> 5, b = ab & 31;

    for (int hp = threadIdx.x; hp < 256; hp += blockDim.x) {
        int h0 = hp*2;
        int r0 = a*H_ + h0, r1 = r0 + 1;
        float c0v = g_cc[r0], c1v = g_cc[r1];
#pragma unroll
        for (int cs = 0; cs < CSPL; cs++) {
            const float* cp = g_cp + ((size_t)(cs*A_ + a)*B_ + b)*H_ + h0;
            c0v += cp[0]; c1v += cp[1];
        }
        float* p = sC + hp*24;
        p[0] = g_M1[r0*2+0]; p[1] = g_M1[r1*2+0];
        p[2] = g_M1[r0*2+1]; p[3] = g_M1[r1*2+1];
#pragma unroll
        for (int f = 0; f < 8; f++) { p[4+2*f] = g_M2[r0*8+f]; p[5+2*f] = g_M2[r1*8+f]; }
        p[20] = c0v; p[21] = c1v; p[22] = va[r0]; p[23] = va[r1];
    }
    __syncthreads();

    int s = half*256 + threadIdx.x*2;
    float2 st0p = *(const float2*)(stat + ((size_t)b*2+0)*S_ + s);
    float2 st1p = *(const float2*)(stat + ((size_t)b*2+1)*S_ + s);
    u64 st0a = bcast2(st0p.x), st0b = bcast2(st0p.y);
    u64 st1a = bcast2(st1p.x), st1b = bcast2(st1p.y);
    u64 dya[8], dyb[8];
#pragma unroll
    for (int f = 0; f < 8; f++) {
        float2 d = *(const float2*)(dyn + (((size_t)a*B_ + b)*FD_ + f)*S_ + s);
        dya[f] = bcast2(d.x); dyb[f] = bcast2(d.y);
    }

    u64 acc0 = 0ull, acc1 = 0ull;
#pragma unroll 2
    for (int hp = 0; hp < 256; hp++) {
        const U2* cp = (const U2*)(sC + hp*24);
        U2 q0 = cp[0], q1 = cp[1], q2 = cp[2], q3 = cp[3], q4 = cp[4], q5 = cp[5];
        // s-slot 0
        u64 u = fma2(q0.x, st0a, q5.x);
        u = fma2(q0.y, st1a, u);
        u = fma2(q1.x, dya[0], u); u = fma2(q1.y, dya[1], u);
        u = fma2(q2.x, dya[2], u); u = fma2(q2.y, dya[3], u);
        u = fma2(q3.x, dya[4], u); u = fma2(q3.y, dya[5], u);
        u = fma2(q4.x, dya[6], u); u = fma2(q4.y, dya[7], u);
        acc0 = fma2(q5.y, tanh2(u), acc0);
        // s-slot 1
        u64 v = fma2(q0.x, st0b, q5.x);
        v = fma2(q0.y, st1b, v);
        v = fma2(q1.x, dyb[0], v); v = fma2(q1.y, dyb[1], v);
        v = fma2(q2.x, dyb[2], v); v = fma2(q2.y, dyb[3], v);
        v = fma2(q3.x, dyb[4], v); v = fma2(q3.y, dyb[5], v);
        v = fma2(q4.x, dyb[6], v); v = fma2(q4.y, dyb[7], v);
        acc1 = fma2(q5.y, tanh2(v), acc1);
    }
    float a0, a1, b0, b1;
    unpack2(acc0, a0, a1);
    unpack2(acc1, b0, b1);
    *(float2*)(g_score + (size_t)ab*S_ + s) = make_float2(a0 + a1, b0 + b1);
}

// =============================================================================
// K4b: softmax over s + p = static @ attn
// =============================================================================
__global__ void k4b_softmax_p(const float* __restrict__ stat) {
    __shared__ float redM[16];
    __shared__ float redS[16][3];
    int ab = blockIdx.x;
    int b = ab & 31;
    int tid = threadIdx.x, warp = tid >> 5, lane = tid & 31;
    float v = g_score[(size_t)ab*S_ + tid];
    float m = v;
#pragma unroll
    for (int o = 16; o; o >>= 1) m = fmaxf(m, __shfl_xor_sync(0xffffffffu, m, o));
    if (lane == 0) redM[warp] = m;
    __syncthreads();
    float mx = redM[0];
#pragma unroll
    for (int w = 1; w < 16; w++) mx = fmaxf(mx, redM[w]);
    float e = __expf(v - mx);
    float st0 = stat[((size_t)b*2+0)*S_ + tid];
    float st1 = stat[((size_t)b*2+1)*S_ + tid];
    float s0 = e, s1 = e*st0, s2 = e*st1;
#pragma unroll
    for (int o = 16; o; o >>= 1) {
        s0 += __shfl_xor_sync(0xffffffffu, s0, o);
        s1 += __shfl_xor_sync(0xffffffffu, s1, o);
        s2 += __shfl_xor_sync(0xffffffffu, s2, o);
    }
    if (lane == 0) { redS[warp][0] = s0; redS[warp][1] = s1; redS[warp][2] = s2; }
    __syncthreads();
    if (tid == 0) {
        float d = 0.f, n0 = 0.f, n1 = 0.f;
#pragma unroll
        for (int w = 0; w < 16; w++) { d += redS[w][0]; n0 += redS[w][1]; n1 += redS[w][2]; }
        g_p2[ab*2+0] = n0 / d;
        g_p2[ab*2+1] = n1 / d;
    }
}

// =============================================================================
// K5: pointer head (f32x2 over h-pairs + tanh.approx)
// grid A*B*2, block 128; smem 256 h-pairs x 8 floats = 8KB
// =============================================================================
__global__ void k5_probs(const float* __restrict__ stat,
                         const float* __restrict__ vp,
                         float* __restrict__ out) {
    __shared__ float sC[256*8];
    int blk = blockIdx.x;
    int half = blk & 1, ab = blk >> 1;
    int a = ab >> 5, b = ab & 31;
    float p0 = g_p2[ab*2+0], p1 = g_p2[ab*2+1];

    for (int hp = threadIdx.x; hp < 256; hp += blockDim.x) {
        int h0 = hp*2;
        int r0 = a*H_ + h0, r1 = r0 + 1;
        float d0 = fmaf(g_N2[r0*2+0], p0, fmaf(g_N2[r0*2+1], p1, g_kk[r0]));
        float d1 = fmaf(g_N2[r1*2+0], p0, fmaf(g_N2[r1*2+1], p1, g_kk[r1]));
        float* p = sC + hp*8;
        p[0] = g_N1[r0*2+0]; p[1] = g_N1[r1*2+0];
        p[2] = g_N1[r0*2+1]; p[3] = g_N1[r1*2+1];
        p[4] = d0; p[5] = d1; p[6] = vp[r0]; p[7] = vp[r1];
    }
    __syncthreads();

    int s = half*256 + threadIdx.x*2;
    float2 st0p = *(const float2*)(stat + ((size_t)b*2+0)*S_ + s);
    float2 st1p = *(const float2*)(stat + ((size_t)b*2+1)*S_ + s);
    u64 st0a = bcast2(st0p.x), st0b = bcast2(st0p.y);
    u64 st1a = bcast2(st1p.x), st1b = bcast2(st1p.y);

    u64 acc0 = 0ull, acc1 = 0ull;
#pragma unroll 4
    for (int hp = 0; hp < 256; hp++) {
        const U2* cp = (const U2*)(sC + hp*8);
        U2 q0 = cp[0], q1 = cp[1];
        u64 u = fma2(q0.x, st0a, q1.x);
        u = fma2(q0.y, st1a, u);
        acc0 = fma2(q1.y, tanh2(u), acc0);
        u64 v = fma2(q0.x, st0b, q1.x);
        v = fma2(q0.y, st1b, v);
        acc1 = fma2(q1.y, tanh2(v), acc1);
    }
    float a0, a1, b0, b1;
    unpack2(acc0, a0, a1);
    unpack2(acc1, b0, b1);
    *(float2*)(out + (size_t)ab*S_ + s) = make_float2(a0 + a1, b0 + b1);
}

// =============================================================================
extern "C" void kernel_launch(void* const* d_in, const int* in_sizes, int n_in,
                              void* d_out, int out_size) {
    const float* stat  = (const float*)d_in[0];
    const float* dyn   = (const float*)d_in[1];
    const float* dec   = (const float*)d_in[2];
    const float* hh    = (const float*)d_in[3];
    const float* Ws    = (const float*)d_in[4];
    const float* bs    = (const float*)d_in[5];
    const float* Wd    = (const float*)d_in[6];
    const float* bd    = (const float*)d_in[7];
    const float* Wdec  = (const float*)d_in[8];
    const float* bdec  = (const float*)d_in[9];
    const float* Wih   = (const float*)d_in[10];
    const float* Whh   = (const float*)d_in[11];
    const float* bih   = (const float*)d_in[12];
    const float* bhh   = (const float*)d_in[13];
    const float* va    = (const float*)d_in[14];
    const float* Wattn = (const float*)d_in[15];
    const float* vp    = (const float*)d_in[16];
    const float* Wptr  = (const float*)d_in[17];
    float* out = (float*)d_out;

    k0a_fold_ih      <<<dim3(192, A_), 256>>>(Wih, Wdec, bdec, bih);
    k0b_fold_attn_ptr<<<dim3(64, A_),  256>>>(Wattn, Wptr, Ws, bs, Wd, bd);
    k1_gh            <<<dim3(12, KSPL, A_), 128>>>(Whh, hh);
    k2_gates         <<<640, 256>>>(dec, hh, bhh, out);
    k3_c             <<<dim3(4, CSPL, A_), 128>>>(Wattn, out);
    k4a_score        <<<A_*B_*2, 128>>>(stat, dyn, va);
    k4b_softmax_p    <<<A_*B_, 512>>>(stat);
    k5_probs         <<<A_*B_*2, 128>>>(stat, vp, out);
}

// round 3
// speedup vs baseline: 1.4229x; 1.0347x over previous
#include <cuda_runtime.h>
#include <cstdint>

// Problem constants
#define A_  10
#define B_  32
#define FS_ 2
#define FD_ 8
#define H_  512
#define H3_ 1536
#define S_  512
#define KSPL 4   // k-split for gh GEMM
#define CSPL 4   // k-split for c GEMM

#define OUT_HH_OFF (A_*B_*S_)   // probs [A,B,S] first, then hh [A,B,H]

typedef unsigned long long u64;

// ---------------- scratch (static device globals; no allocation) -------------
__device__ float g_M1[A_*H_*2];
__device__ float g_M2[A_*H_*8];
__device__ float g_cc[A_*H_];
__device__ float g_N1[A_*H_*2];
__device__ float g_N2[A_*H_*2];
__device__ float g_kk[A_*H_];
__device__ float g_P [A_*H3_*2];
__device__ float g_q [A_*H3_];
__device__ float g_ghp[KSPL*A_*B_*H3_];
__device__ float g_cp [CSPL*A_*B_*H_];
__device__ float g_score[A_*B_*S_];

// ---------------- math helpers ----------------------------------------------
struct __align__(16) U2 { u64 x, y; };

__device__ __forceinline__ u64 pack2(float lo, float hi) {
    u64 r; asm("mov.b64 %0, {%1,%2};" : "=l"(r) : "f"(lo), "f"(hi)); return r;
}
__device__ __forceinline__ u64 bcast2(float x) { return pack2(x, x); }
__device__ __forceinline__ void unpack2(u64 v, float& lo, float& hi) {
    asm("mov.b64 {%0,%1}, %2;" : "=f"(lo), "=f"(hi) : "l"(v));
}
__device__ __forceinline__ u64 fma2(u64 a, u64 b, u64 c) {
    u64 d; asm("fma.rn.f32x2 %0, %1, %2, %3;" : "=l"(d) : "l"(a), "l"(b), "l"(c));
    return d;
}
__device__ __forceinline__ float tanh_ap(float x) {
    float y; asm("tanh.approx.f32 %0, %1;" : "=f"(y) : "f"(x)); return y;
}
__device__ __forceinline__ u64 tanh2(u64 v) {
    float a, b; unpack2(v, a, b);
    return pack2(tanh_ap(a), tanh_ap(b));
}
__device__ __forceinline__ float ftanh(float x) {
    x = fminf(fmaxf(x, -15.f), 15.f);
    float t = __expf(x + x);
    return fmaf(-2.f, __fdividef(1.f, t + 1.f), 1.f);
}
__device__ __forceinline__ float sigm(float x) {
    return __fdividef(1.f, 1.f + __expf(-x));
}

// =============================================================================
// K0a: fold Wih -> P [3H,2], q [3H]   (per agent)
// =============================================================================
__global__ void k0a_fold_ih(const float* __restrict__ Wih,
                            const float* __restrict__ Wdec,
                            const float* __restrict__ bdec,
                            const float* __restrict__ bih) {
    int a = blockIdx.y;
    __shared__ float4 sDec[H_];
    for (int k = threadIdx.x; k < H_; k += blockDim.x) {
        sDec[k] = make_float4(Wdec[((size_t)a*H_ + k)*2 + 0],
                              Wdec[((size_t)a*H_ + k)*2 + 1],
                              bdec[(size_t)a*H_ + k], 0.f);
    }
    __syncthreads();
    int warp = threadIdx.x >> 5, lane = threadIdx.x & 31;
    int j = blockIdx.x * 8 + warp;
    const float* row = Wih + ((size_t)a*H3_ + j)*H_;
    float p0 = 0.f, p1 = 0.f, q = 0.f;
#pragma unroll
    for (int i = 0; i < 4; i++) {
        int k0 = lane*4 + i*128;
        float4 w4 = *(const float4*)(row + k0);
        float4 d0 = sDec[k0+0], d1 = sDec[k0+1], d2 = sDec[k0+2], d3 = sDec[k0+3];
        p0 = fmaf(w4.x,d0.x, fmaf(w4.y,d1.x, fmaf(w4.z,d2.x, fmaf(w4.w,d3.x, p0))));
        p1 = fmaf(w4.x,d0.y, fmaf(w4.y,d1.y, fmaf(w4.z,d2.y, fmaf(w4.w,d3.y, p1))));
        q  = fmaf(w4.x,d0.z, fmaf(w4.y,d1.z, fmaf(w4.z,d2.z, fmaf(w4.w,d3.z, q ))));
    }
#pragma unroll
    for (int o = 16; o; o >>= 1) {
        p0 += __shfl_down_sync(0xffffffffu, p0, o);
        p1 += __shfl_down_sync(0xffffffffu, p1, o);
        q  += __shfl_down_sync(0xffffffffu, q , o);
    }
    if (lane == 0) {
        int r = a*H3_ + j;
        g_P[r*2+0] = p0; g_P[r*2+1] = p1;
        g_q[r] = q + bih[r];
    }
}

// =============================================================================
// K0b: fold W_attn -> M1,M2,cc   and W_ptr -> N1,N2,kk
// =============================================================================
__global__ void k0b_fold_attn_ptr(const float* __restrict__ Wattn,
                                  const float* __restrict__ Wptr,
                                  const float* __restrict__ Ws,
                                  const float* __restrict__ bs,
                                  const float* __restrict__ Wd,
                                  const float* __restrict__ bd) {
    int a = blockIdx.y;
    __shared__ float4 sFold[H_];
    __shared__ float4 sWdA[H_], sWdB[H_];
    for (int k = threadIdx.x; k < H_; k += blockDim.x) {
        sFold[k] = make_float4(Ws[k*2+0], Ws[k*2+1], bs[k], bd[(size_t)a*H_ + k]);
        const float* wd = Wd + ((size_t)a*H_ + k)*8;
        sWdA[k] = *(const float4*)(wd);
        sWdB[k] = *(const float4*)(wd + 4);
    }
    __syncthreads();
    int warp = threadIdx.x >> 5, lane = threadIdx.x & 31;
    int h = blockIdx.x * 8 + warp;
    const float* ra = Wattn + ((size_t)a*H_ + h)*H3_;
    const float* rp = Wptr  + ((size_t)a*H_ + h)*(2*H_);
    float acc[16];
#pragma unroll
    for (int t = 0; t < 16; t++) acc[t] = 0.f;
#pragma unroll
    for (int i = 0; i < 4; i++) {
        int k0 = lane*4 + i*128;
        float4 a1 = *(const float4*)(ra + k0);
        float4 a2 = *(const float4*)(ra + H_ + k0);
        float4 q1 = *(const float4*)(rp + k0);
        float4 q2 = *(const float4*)(rp + H_ + k0);
        const float* a1p = (const float*)&a1;
        const float* a2p = (const float*)&a2;
        const float* q1p = (const float*)&q1;
        const float* q2p = (const float*)&q2;
#pragma unroll
        for (int c = 0; c < 4; c++) {
            int k = k0 + c;
            float wa1 = a1p[c], wa2 = a2p[c], wp1 = q1p[c], wp2 = q2p[c];
            float4 f  = sFold[k];
            float4 dA = sWdA[k];
            float4 dB = sWdB[k];
            acc[0]  = fmaf(wa1, f.x, acc[0]);
            acc[1]  = fmaf(wa1, f.y, acc[1]);
            acc[2]  = fmaf(wa2, dA.x, acc[2]);
            acc[3]  = fmaf(wa2, dA.y, acc[3]);
            acc[4]  = fmaf(wa2, dA.z, acc[4]);
            acc[5]  = fmaf(wa2, dA.w, acc[5]);
            acc[6]  = fmaf(wa2, dB.x, acc[6]);
            acc[7]  = fmaf(wa2, dB.y, acc[7]);
            acc[8]  = fmaf(wa2, dB.z, acc[8]);
            acc[9]  = fmaf(wa2, dB.w, acc[9]);
            acc[10] = fmaf(wa1, f.z, fmaf(wa2, f.w, acc[10]));
            acc[11] = fmaf(wp1, f.x, acc[11]);
            acc[12] = fmaf(wp1, f.y, acc[12]);
            acc[13] = fmaf(wp2, f.x, acc[13]);
            acc[14] = fmaf(wp2, f.y, acc[14]);
            acc[15] = fmaf(wp1 + wp2, f.z, acc[15]);
        }
    }
#pragma unroll
    for (int t = 0; t < 16; t++)
#pragma unroll
        for (int o = 16; o; o >>= 1)
            acc[t] += __shfl_down_sync(0xffffffffu, acc[t], o);
    if (lane == 0) {
        int r = a*H_ + h;
        g_M1[r*2+0] = acc[0];  g_M1[r*2+1] = acc[1];
#pragma unroll
        for (int f2 = 0; f2 < 8; f2++) g_M2[r*8+f2] = acc[2+f2];
        g_cc[r] = acc[10];
        g_N1[r*2+0] = acc[11]; g_N1[r*2+1] = acc[12];
        g_N2[r*2+0] = acc[13]; g_N2[r*2+1] = acc[14];
        g_kk[r] = acc[15];
    }
}

// =============================================================================
// K1: gh partials, f32x2 over b-pairs
// grid (12, KSPL, A), block 128
// =============================================================================
__global__ void k1_gh(const float* __restrict__ Whh,
                      const float* __restrict__ hh) {
    int a = blockIdx.z, ks = blockIdx.y;
    int k0 = ks * 128;
    __shared__ __align__(16) u64 sHH[128*16];   // [kl][b-pair]
    for (int idx = threadIdx.x; idx < 16*128; idx += 128) {
        int bp = idx >> 7, kl = idx & 127;
        sHH[kl*16 + bp] = pack2(hh[(size_t)(2*bp  )*H_ + k0 + kl],
                                hh[(size_t)(2*bp+1)*H_ + k0 + kl]);
    }
    __syncthreads();
    int j = blockIdx.x * 128 + threadIdx.x;
    const float* row = Whh + ((size_t)a*H3_ + j)*H_ + k0;
    u64 acc[16];
#pragma unroll
    for (int t = 0; t < 16; t++) acc[t] = 0ull;

    for (int kl = 0; kl < 128; kl += 4) {
        float4 w4 = *(const float4*)(row + kl);
        const float* wp = (const float*)&w4;
#pragma unroll
        for (int c = 0; c < 4; c++) {
            u64 w2 = bcast2(wp[c]);
            const U2* hp = (const U2*)(sHH + (kl + c)*16);
#pragma unroll
            for (int bi = 0; bi < 8; bi++) {
                U2 h2 = hp[bi];
                acc[bi*2+0] = fma2(w2, h2.x, acc[bi*2+0]);
                acc[bi*2+1] = fma2(w2, h2.y, acc[bi*2+1]);
            }
        }
    }
    float* outp = g_ghp + ((size_t)(ks*A_ + a)*B_)*H3_ + j;
#pragma unroll
    for (int bp = 0; bp < 16; bp++) {
        float lo, hi; unpack2(acc[bp], lo, hi);
        outp[(size_t)(2*bp  )*H3_] = lo;
        outp[(size_t)(2*bp+1)*H3_] = hi;
    }
}

// =============================================================================
// K2: GRU gates -> h_new (precise math; output)
// =============================================================================
__global__ void k2_gates(const float* __restrict__ dec,
                         const float* __restrict__ hh,
                         const float* __restrict__ bhh,
                         float* __restrict__ out) {
    int idx = blockIdx.x * blockDim.x + threadIdx.x;
    int h  = idx & (H_-1);
    int ab = idx >> 9;
    int b  = ab & (B_-1);
    int a  = ab >> 5;
    float d0 = dec[b*2+0], d1 = dec[b*2+1];
    int base = a*H3_;

    float gi[3], gh[3];
#pragma unroll
    for (int g = 0; g < 3; g++) {
        int j = base + g*H_ + h;
        gi[g] = fmaf(g_P[j*2+0], d0, fmaf(g_P[j*2+1], d1, g_q[j]));
        float s = bhh[j];
#pragma unroll
        for (int ks = 0; ks < KSPL; ks++)
            s += g_ghp[((size_t)(ks*A_ + a)*B_ + b)*H3_ + g*H_ + h];
        gh[g] = s;
    }
    float r = sigm(gi[0] + gh[0]);
    float z = sigm(gi[1] + gh[1]);
    float n = ftanh(fmaf(r, gh[2], gi[2]));
    float hprev = hh[(size_t)b*H_ + h];
    out[OUT_HH_OFF + (size_t)ab*H_ + h] = fmaf(z, hprev - n, n);
}

// =============================================================================
// K3: c partials, f32x2 over b-pairs
// grid (4, CSPL, A), block 128
// =============================================================================
__global__ void k3_c(const float* __restrict__ Wattn,
                     const float* __restrict__ out) {
    int a = blockIdx.z, cs = blockIdx.y;
    int k0 = cs * 128;
    __shared__ __align__(16) u64 sHN[128*16];
    const float* hn = out + OUT_HH_OFF + (size_t)a*B_*H_;
    for (int idx = threadIdx.x; idx < 16*128; idx += 128) {
        int bp = idx >> 7, kl = idx & 127;
        sHN[kl*16 + bp] = pack2(hn[(size_t)(2*bp  )*H_ + k0 + kl],
                                hn[(size_t)(2*bp+1)*H_ + k0 + kl]);
    }
    __syncthreads();
    int h = blockIdx.x * 128 + threadIdx.x;
    const float* row = Wattn + ((size_t)a*H_ + h)*H3_ + 2*H_ + k0;
    u64 acc[16];
#pragma unroll
    for (int t = 0; t < 16; t++) acc[t] = 0ull;

    for (int kl = 0; kl < 128; kl += 4) {
        float4 w4 = *(const float4*)(row + kl);
        const float* wp = (const float*)&w4;
#pragma unroll
        for (int c = 0; c < 4; c++) {
            u64 w2 = bcast2(wp[c]);
            const U2* hp = (const U2*)(sHN + (kl + c)*16);
#pragma unroll
            for (int bi = 0; bi < 8; bi++) {
                U2 h2 = hp[bi];
                acc[bi*2+0] = fma2(w2, h2.x, acc[bi*2+0]);
                acc[bi*2+1] = fma2(w2, h2.y, acc[bi*2+1]);
            }
        }
    }
    float* outp = g_cp + ((size_t)(cs*A_ + a)*B_)*H_ + h;
#pragma unroll
    for (int bp = 0; bp < 16; bp++) {
        float lo, hi; unpack2(acc[bp], lo, hi);
        outp[(size_t)(2*bp  )*H_] = lo;
        outp[(size_t)(2*bp+1)*H_] = hi;
    }
}

// =============================================================================
// K4a: attention scores (f32x2 over h-pairs + tanh.approx)
// grid A*B*2 (s halves), block 128
// =============================================================================
__global__ void k4a_score(const float* __restrict__ stat,
                          const float* __restrict__ dyn,
                          const float* __restrict__ va) {
    __shared__ float sC[256*24];
    int blk = blockIdx.x;
    int half = blk & 1, ab = blk >> 1;
    int a = ab >> 5, b = ab & 31;

    for (int hp = threadIdx.x; hp < 256; hp += blockDim.x) {
        int h0 = hp*2;
        int r0 = a*H_ + h0, r1 = r0 + 1;
        float c0v = g_cc[r0], c1v = g_cc[r1];
#pragma unroll
        for (int cs = 0; cs < CSPL; cs++) {
            const float* cp = g_cp + ((size_t)(cs*A_ + a)*B_ + b)*H_ + h0;
            c0v += cp[0]; c1v += cp[1];
        }
        float* p = sC + hp*24;
        p[0] = g_M1[r0*2+0]; p[1] = g_M1[r1*2+0];
        p[2] = g_M1[r0*2+1]; p[3] = g_M1[r1*2+1];
#pragma unroll
        for (int f = 0; f < 8; f++) { p[4+2*f] = g_M2[r0*8+f]; p[5+2*f] = g_M2[r1*8+f]; }
        p[20] = c0v; p[21] = c1v; p[22] = va[r0]; p[23] = va[r1];
    }
    __syncthreads();

    int s = half*256 + threadIdx.x*2;
    float2 st0p = *(const float2*)(stat + ((size_t)b*2+0)*S_ + s);
    float2 st1p = *(const float2*)(stat + ((size_t)b*2+1)*S_ + s);
    u64 st0a = bcast2(st0p.x), st0b = bcast2(st0p.y);
    u64 st1a = bcast2(st1p.x), st1b = bcast2(st1p.y);
    u64 dya[8], dyb[8];
#pragma unroll
    for (int f = 0; f < 8; f++) {
        float2 d = *(const float2*)(dyn + (((size_t)a*B_ + b)*FD_ + f)*S_ + s);
        dya[f] = bcast2(d.x); dyb[f] = bcast2(d.y);
    }

    u64 acc0 = 0ull, acc1 = 0ull;
#pragma unroll 2
    for (int hp = 0; hp < 256; hp++) {
        const U2* cp = (const U2*)(sC + hp*24);
        U2 q0 = cp[0], q1 = cp[1], q2 = cp[2], q3 = cp[3], q4 = cp[4], q5 = cp[5];
        u64 u = fma2(q0.x, st0a, q5.x);
        u = fma2(q0.y, st1a, u);
        u = fma2(q1.x, dya[0], u); u = fma2(q1.y, dya[1], u);
        u = fma2(q2.x, dya[2], u); u = fma2(q2.y, dya[3], u);
        u = fma2(q3.x, dya[4], u); u = fma2(q3.y, dya[5], u);
        u = fma2(q4.x, dya[6], u); u = fma2(q4.y, dya[7], u);
        acc0 = fma2(q5.y, tanh2(u), acc0);
        u64 v = fma2(q0.x, st0b, q5.x);
        v = fma2(q0.y, st1b, v);
        v = fma2(q1.x, dyb[0], v); v = fma2(q1.y, dyb[1], v);
        v = fma2(q2.x, dyb[2], v); v = fma2(q2.y, dyb[3], v);
        v = fma2(q3.x, dyb[4], v); v = fma2(q3.y, dyb[5], v);
        v = fma2(q4.x, dyb[6], v); v = fma2(q4.y, dyb[7], v);
        acc1 = fma2(q5.y, tanh2(v), acc1);
    }
    float a0, a1, b0, b1;
    unpack2(acc0, a0, a1);
    unpack2(acc1, b0, b1);
    *(float2*)(g_score + (size_t)ab*S_ + s) = make_float2(a0 + a1, b0 + b1);
}

// =============================================================================
// K5: softmax + context + pointer head, one block per (a,b)
// grid A*B, block 256 (each thread handles s = 2t, 2t+1)
// =============================================================================
__global__ void k5_probs(const float* __restrict__ stat,
                         const float* __restrict__ vp,
                         float* __restrict__ out) {
    __shared__ float sC[256*8];
    __shared__ float red[32];
    __shared__ float sP[2];
    int ab = blockIdx.x;
    int a = ab >> 5, b = ab & 31;
    int tid = threadIdx.x, warp = tid >> 5, lane = tid & 31;
    int s = tid*2;

    float2 sc   = *(const float2*)(g_score + (size_t)ab*S_ + s);
    float2 st0p = *(const float2*)(stat + ((size_t)b*2+0)*S_ + s);
    float2 st1p = *(const float2*)(stat + ((size_t)b*2+1)*S_ + s);

    // block max
    float m = fmaxf(sc.x, sc.y);
#pragma unroll
    for (int o = 16; o; o >>= 1) m = fmaxf(m, __shfl_xor_sync(0xffffffffu, m, o));
    if (lane == 0) red[warp] = m;
    __syncthreads();
    float mx = red[0];
#pragma unroll
    for (int w = 1; w < 8; w++) mx = fmaxf(mx, red[w]);
    __syncthreads();

    float e0 = __expf(sc.x - mx), e1 = __expf(sc.y - mx);
    float d  = e0 + e1;
    float n0 = fmaf(e0, st0p.x, e1*st0p.y);
    float n1 = fmaf(e0, st1p.x, e1*st1p.y);
#pragma unroll
    for (int o = 16; o; o >>= 1) {
        d  += __shfl_xor_sync(0xffffffffu, d , o);
        n0 += __shfl_xor_sync(0xffffffffu, n0, o);
        n1 += __shfl_xor_sync(0xffffffffu, n1, o);
    }
    if (lane == 0) { red[warp] = d; red[8+warp] = n0; red[16+warp] = n1; }
    __syncthreads();
    if (tid == 0) {
        float D = 0.f, N0 = 0.f, N1 = 0.f;
#pragma unroll
        for (int w = 0; w < 8; w++) { D += red[w]; N0 += red[8+w]; N1 += red[16+w]; }
        sP[0] = N0 / D; sP[1] = N1 / D;
    }
    __syncthreads();
    float p0 = sP[0], p1 = sP[1];

    // fill pointer constants (one hp per thread)
    {
        int hp = tid, h0 = hp*2;
        int r0 = a*H_ + h0, r1 = r0 + 1;
        float d0 = fmaf(g_N2[r0*2+0], p0, fmaf(g_N2[r0*2+1], p1, g_kk[r0]));
        float d1 = fmaf(g_N2[r1*2+0], p0, fmaf(g_N2[r1*2+1], p1, g_kk[r1]));
        float* p = sC + hp*8;
        p[0] = g_N1[r0*2+0]; p[1] = g_N1[r1*2+0];
        p[2] = g_N1[r0*2+1]; p[3] = g_N1[r1*2+1];
        p[4] = d0; p[5] = d1; p[6] = vp[r0]; p[7] = vp[r1];
    }
    __syncthreads();

    u64 st0a = bcast2(st0p.x), st0b = bcast2(st0p.y);
    u64 st1a = bcast2(st1p.x), st1b = bcast2(st1p.y);

    u64 acc0 = 0ull, acc1 = 0ull;
#pragma unroll 4
    for (int hp = 0; hp < 256; hp++) {
        const U2* cp = (const U2*)(sC + hp*8);
        U2 q0 = cp[0], q1 = cp[1];
        u64 u = fma2(q0.x, st0a, q1.x);
        u = fma2(q0.y, st1a, u);
        acc0 = fma2(q1.y, tanh2(u), acc0);
        u64 v = fma2(q0.x, st0b, q1.x);
        v = fma2(q0.y, st1b, v);
        acc1 = fma2(q1.y, tanh2(v), acc1);
    }
    float a0, a1, b0, b1;
    unpack2(acc0, a0, a1);
    unpack2(acc1, b0, b1);
    *(float2*)(out + (size_t)ab*S_ + s) = make_float2(a0 + a1, b0 + b1);
}

// =============================================================================
extern "C" void kernel_launch(void* const* d_in, const int* in_sizes, int n_in,
                              void* d_out, int out_size) {
    const float* stat  = (const float*)d_in[0];
    const float* dyn   = (const float*)d_in[1];
    const float* dec   = (const float*)d_in[2];
    const float* hh    = (const float*)d_in[3];
    const float* Ws    = (const float*)d_in[4];
    const float* bs    = (const float*)d_in[5];
    const float* Wd    = (const float*)d_in[6];
    const float* bd    = (const float*)d_in[7];
    const float* Wdec  = (const float*)d_in[8];
    const float* bdec  = (const float*)d_in[9];
    const float* Wih   = (const float*)d_in[10];
    const float* Whh   = (const float*)d_in[11];
    const float* bih   = (const float*)d_in[12];
    const float* bhh   = (const float*)d_in[13];
    const float* va    = (const float*)d_in[14];
    const float* Wattn = (const float*)d_in[15];
    const float* vp    = (const float*)d_in[16];
    const float* Wptr  = (const float*)d_in[17];
    float* out = (float*)d_out;

    // one-time infra (host objects only; no device memory)
    static cudaStream_t sA = nullptr, sB = nullptr;
    static cudaEvent_t evRoot = nullptr, evA = nullptr, evB = nullptr;
    if (sA == nullptr) {
        cudaStreamCreateWithFlags(&sA, cudaStreamNonBlocking);
        cudaStreamCreateWithFlags(&sB, cudaStreamNonBlocking);
        cudaEventCreateWithFlags(&evRoot, cudaEventDisableTiming);
        cudaEventCreateWithFlags(&evA, cudaEventDisableTiming);
        cudaEventCreateWithFlags(&evB, cudaEventDisableTiming);
    }

    // fork side streams off the main (captured) stream
    cudaEventRecord(evRoot, 0);
    cudaStreamWaitEvent(sA, evRoot, 0);
    cudaStreamWaitEvent(sB, evRoot, 0);

    k0a_fold_ih      <<<dim3(192, A_), 256, 0, sA>>>(Wih, Wdec, bdec, bih);
    cudaEventRecord(evA, sA);
    k0b_fold_attn_ptr<<<dim3(64, A_),  256, 0, sB>>>(Wattn, Wptr, Ws, bs, Wd, bd);
    cudaEventRecord(evB, sB);

    k1_gh            <<<dim3(12, KSPL, A_), 128>>>(Whh, hh);
    cudaStreamWaitEvent(0, evA, 0);              // k2 needs k0a (+k1)
    k2_gates         <<<640, 256>>>(dec, hh, bhh, out);
    k3_c             <<<dim3(4, CSPL, A_), 128>>>(Wattn, out);
    cudaStreamWaitEvent(0, evB, 0);              // k4a/k5 need k0b
    k4a_score        <<<A_*B_*2, 128>>>(stat, dyn, va);
    k5_probs         <<<A_*B_, 256>>>(stat, vp, out);
}